// round 16
// baseline (speedup 1.0000x reference)
#include <cuda_runtime.h>

// CharRNN on GB300 — R16.
// R13 post-mortem: neither fma pipe (37.6%) nor issue (43.6%) saturated at 10
// warps => latency-bound; broadcast LDS is free (cost = inst issue, not bytes),
// so more warps is the lever. Changes:
//  (1) CP=4, NG=52, NTHR=416 (13 warps, +30% occupancy); W_h slice = 100 regs,
//      peak live ~150 < 157 cap (spill-free).
//  (2) Reduce-scatter on PACKED f32x2 {row0,row1} values: 8 U64 slots, 3 rounds,
//      7 slot-ops (SEL64+SHFL64+add.rn.f32x2) vs 52 scalar inst.
//  (3) tokens packed int2 (one LDS.64), WoS clamped to 33 groups (48KB limit).

#define H     200
#define NROW  2
#define SEQ   1024
#define VOCAB 33
#define BATCH 256
#define KC    8
#define KPT   25
#define CPAD  28           // padded chunk stride in hbuf (floats)
#define CP    4
#define NG    52           // col groups; jg 50,51 are pure padding
#define NTHR  416

__device__ float g_EWe[VOCAB * H];

union U64 { unsigned long long u; float2 f; };

__device__ __forceinline__ void ffma2(U64 &acc, U64 a, U64 b) {
    asm("fma.rn.f32x2 %0, %1, %2, %0;" : "+l"(acc.u) : "l"(a.u), "l"(b.u));
}
__device__ __forceinline__ U64 add2(U64 a, U64 b) {
    U64 r;
    asm("add.rn.f32x2 %0, %1, %2;" : "=l"(r.u) : "l"(a.u), "l"(b.u));
    return r;
}
__device__ __forceinline__ float fast_tanh(float v) {
    v = fminf(15.f, fmaxf(-15.f, v));
    float e = __expf(2.f * v);
    return __fdividef(e - 1.f, e + 1.f);
}

__global__ void prep_kernel(const float* __restrict__ emb,
                            const float* __restrict__ We) {
    int v = blockIdx.x;
    int j = threadIdx.x;
    float acc = 0.f;
    #pragma unroll 4
    for (int e = 0; e < H; e++)
        acc = fmaf(emb[v * H + e], We[e * H + j], acc);
    g_EWe[v * H + j] = acc;
}

__global__ void __launch_bounds__(NTHR, 1) rnn_kernel(
    const int* __restrict__ x, const float* __restrict__ h0,
    const float* __restrict__ Wh, const float* __restrict__ Wo,
    float* __restrict__ out, int out_elems)
{
    __shared__ float  hbuf[2][NROW][KC * CPAD];  // chunk-padded h, double-buffered
    __shared__ int2   tok2[SEQ];                 // {row0,row1} tokens
    __shared__ float2 WoS[VOCAB][KC][13];        // W_o^T slices

    const int tid  = threadIdx.x;
    const int lane = tid & 31;
    const int warp = tid >> 5;
    const int kc   = lane & 7;          // K-chunk, lane bits 0-2
    const int sub  = lane >> 3;
    const int jg   = warp * 4 + sub;    // col group 0..51 (50,51 = padding)
    const int jgw  = (jg < VOCAB) ? jg : 0;   // clamped for WoS reads
    const int b0   = blockIdx.x * NROW;

    // ---- init hbuf (both buffers incl. zero pads), tokens, WoS ----
    for (int idx = tid; idx < 2 * NROW * KC * CPAD; idx += NTHR) {
        int buf = idx / (NROW * KC * CPAD);
        int rem = idx - buf * (NROW * KC * CPAD);
        int r   = rem / (KC * CPAD);
        int cc  = rem - r * (KC * CPAD);
        int ch  = cc / CPAD, off = cc - ch * CPAD;
        float v = 0.f;
        if (buf == 0 && off < KPT) v = h0[(b0 + r) * H + ch * KPT + off];
        (&hbuf[0][0][0])[idx] = v;
    }
    for (int idx = tid; idx < SEQ; idx += NTHR)
        tok2[idx] = make_int2(x[b0 * SEQ + idx], x[(b0 + 1) * SEQ + idx]);
    for (int idx = tid; idx < VOCAB * KC * 13; idx += NTHR) {
        int v = idx / (KC * 13);
        int rem = idx - v * (KC * 13);
        int k = rem / 13, m = rem - k * 13;
        int k0 = k * KPT + 2 * m;
        float a = Wo[k0 * VOCAB + v];
        float b = (2 * m + 1 < KPT) ? Wo[(k0 + 1) * VOCAB + v] : 0.f;
        WoS[v][k][m] = make_float2(a, b);
    }

    // ---- W_h slice -> registers: 12 pairs + scalar tail per column ----
    U64 wp[CP][12];
    float w24[CP];
    #pragma unroll
    for (int c = 0; c < CP; c++) {
        int j = jg * CP + c;
        bool valid = (j < H);
        #pragma unroll
        for (int m = 0; m < 12; m++) {
            int k0 = kc * KPT + 2 * m;
            wp[c][m].f = valid ? make_float2(Wh[k0 * H + j], Wh[(k0 + 1) * H + j])
                               : make_float2(0.f, 0.f);
        }
        w24[c] = valid ? Wh[(kc * KPT + 24) * H + j] : 0.f;
    }

    // ---- ownership after reduce-scatter: lane kc owns value kc ----
    //   kc<4 : column jg*4+kc (both rows, packed)   kc==4 : both logits
    const bool own = (kc < CP) && (jg < 50);
    const int  jmy = own ? (jg * CP + kc) : 0;
    const int  wmy = (jmy / KPT) * CPAD + (jmy % KPT);
    const bool log_lane = (kc == 4) && (jg < VOCAB);

    __syncthreads();

    int cur = 0;
    for (int t = 0; t < SEQ; t++) {
        // xw prefetch for the owned column (L1-resident table)
        float xw0 = 0.f, xw1 = 0.f;
        if (own) {
            int2 tp = tok2[t];
            xw0 = g_EWe[tp.x * H + jmy];
            xw1 = g_EWe[tp.y * H + jmy];
        }

        // ---- matvec + logits partials (branch-free) ----
        const ulonglong2* a0 = (const ulonglong2*)&hbuf[cur][0][kc * CPAD];
        const ulonglong2* a1 = (const ulonglong2*)&hbuf[cur][1][kc * CPAD];
        const float2* wo = &WoS[jgw][kc][0];
        U64 acc[CP][2];
        #pragma unroll
        for (int c = 0; c < CP; c++) { acc[c][0].u = 0ull; acc[c][1].u = 0ull; }
        U64 l0, l1; l0.u = l1.u = 0ull;

        #pragma unroll
        for (int m4 = 0; m4 < 6; m4++) {
            ulonglong2 q0 = a0[m4];      // LDS.128 -> two ready f32x2 operands
            ulonglong2 q1 = a1[m4];
            U64 p00, p01, p10, p11;
            p00.u = q0.x; p01.u = q0.y;
            p10.u = q1.x; p11.u = q1.y;
            #pragma unroll
            for (int c = 0; c < CP; c++) {
                ffma2(acc[c][0], p00, wp[c][2 * m4]);
                ffma2(acc[c][0], p01, wp[c][2 * m4 + 1]);
                ffma2(acc[c][1], p10, wp[c][2 * m4]);
                ffma2(acc[c][1], p11, wp[c][2 * m4 + 1]);
            }
            U64 wv0, wv1;
            wv0.u = *(const unsigned long long*)&wo[2 * m4];
            wv1.u = *(const unsigned long long*)&wo[2 * m4 + 1];
            ffma2(l0, p00, wv0);
            ffma2(l0, p01, wv1);
            ffma2(l1, p10, wv0);
            ffma2(l1, p11, wv1);
        }
        // K tail (element 24), scalar
        float h0t  = hbuf[cur][0][kc * CPAD + 24];
        float h1t  = hbuf[cur][1][kc * CPAD + 24];
        float wo24 = wo[12].x;

        // ---- fold into packed {row0,row1} slots ----
        U64 s2[8];
        #pragma unroll
        for (int c = 0; c < CP; c++) {
            s2[c].f.x = (acc[c][0].f.x + acc[c][0].f.y) + h0t * w24[c];
            s2[c].f.y = (acc[c][1].f.x + acc[c][1].f.y) + h1t * w24[c];
        }
        s2[4].f.x = (l0.f.x + l0.f.y) + h0t * wo24;
        s2[4].f.y = (l1.f.x + l1.f.y) + h1t * wo24;
        s2[5].u = 0ull; s2[6].u = 0ull; s2[7].u = 0ull;

        // ---- packed reduce-scatter over kc bits: 7 slot-ops ----
        #pragma unroll
        for (int i = 0; i < 4; i++) {
            U64 snd; snd.u = (kc & 4) ? s2[i].u : s2[i + 4].u;
            U64 rcv; rcv.u = __shfl_xor_sync(0xFFFFFFFFu, snd.u, 4);
            U64 keep; keep.u = (kc & 4) ? s2[i + 4].u : s2[i].u;
            s2[i] = add2(keep, rcv);
        }
        #pragma unroll
        for (int i = 0; i < 2; i++) {
            U64 snd; snd.u = (kc & 2) ? s2[i].u : s2[i + 2].u;
            U64 rcv; rcv.u = __shfl_xor_sync(0xFFFFFFFFu, snd.u, 2);
            U64 keep; keep.u = (kc & 2) ? s2[i + 2].u : s2[i].u;
            s2[i] = add2(keep, rcv);
        }
        {
            U64 snd; snd.u = (kc & 1) ? s2[0].u : s2[1].u;
            U64 rcv; rcv.u = __shfl_xor_sync(0xFFFFFFFFu, snd.u, 1);
            U64 keep; keep.u = (kc & 1) ? s2[1].u : s2[0].u;
            s2[0] = add2(keep, rcv);
        }
        // lane kc: s2[0] = value kc.  kc<4: {y_r0,y_r1} for col jmy; kc==4: {L0,L1}

        if (t && log_lane) {
            out[((long long)(b0 + 0) * SEQ + (t - 1)) * VOCAB + jg] = s2[0].f.x;
            out[((long long)(b0 + 1) * SEQ + (t - 1)) * VOCAB + jg] = s2[0].f.y;
        }

        const int nxt = cur ^ 1;
        if (own) {
            U64 xwp; xwp.f = make_float2(xw0, xw1);
            U64 z = add2(s2[0], xwp);
            hbuf[nxt][0][wmy] = fast_tanh(z.f.x);
            hbuf[nxt][1][wmy] = fast_tanh(z.f.y);
        }
        __syncthreads();
        cur = nxt;
    }

    // ---- epilogue: logits for h_{SEQ-1} ----
    {
        const ulonglong2* a0 = (const ulonglong2*)&hbuf[cur][0][kc * CPAD];
        const ulonglong2* a1 = (const ulonglong2*)&hbuf[cur][1][kc * CPAD];
        const float2* wo = &WoS[jgw][kc][0];
        U64 l0, l1; l0.u = l1.u = 0ull;
        #pragma unroll
        for (int m4 = 0; m4 < 6; m4++) {
            ulonglong2 q0 = a0[m4];
            ulonglong2 q1 = a1[m4];
            U64 p00, p01, p10, p11;
            p00.u = q0.x; p01.u = q0.y;
            p10.u = q1.x; p11.u = q1.y;
            U64 wv0, wv1;
            wv0.u = *(const unsigned long long*)&wo[2 * m4];
            wv1.u = *(const unsigned long long*)&wo[2 * m4 + 1];
            ffma2(l0, p00, wv0);
            ffma2(l0, p01, wv1);
            ffma2(l1, p10, wv0);
            ffma2(l1, p11, wv1);
        }
        float h0t  = hbuf[cur][0][kc * CPAD + 24];
        float h1t  = hbuf[cur][1][kc * CPAD + 24];
        float wo24 = wo[12].x;
        float L0 = (l0.f.x + l0.f.y) + h0t * wo24;
        float L1 = (l1.f.x + l1.f.y) + h1t * wo24;
        #pragma unroll
        for (int d = 1; d < 8; d <<= 1) {
            L0 += __shfl_xor_sync(0xFFFFFFFFu, L0, d);
            L1 += __shfl_xor_sync(0xFFFFFFFFu, L1, d);
        }
        if (log_lane) {
            out[((long long)(b0 + 0) * SEQ + (SEQ - 1)) * VOCAB + jg] = L0;
            out[((long long)(b0 + 1) * SEQ + (SEQ - 1)) * VOCAB + jg] = L1;
        }
    }

    // ---- final hidden (second output, if present in d_out) ----
    long long base = (long long)BATCH * SEQ * VOCAB;
    if ((long long)out_elems >= base + (long long)BATCH * H) {
        for (int idx = tid; idx < NROW * H; idx += NTHR) {
            int r = idx / H, jj = idx - r * H;
            out[base + (long long)(b0 + r) * H + jj]
                = hbuf[cur][r][(jj / KPT) * CPAD + (jj % KPT)];
        }
    }
}

extern "C" void kernel_launch(void* const* d_in, const int* in_sizes, int n_in,
                              void* d_out, int out_size) {
    // metadata order: x(int32), hidden, embedding, W_e, W_h, W_o
    const int*   x      = (const int*)d_in[0];
    const float* hidden = (const float*)d_in[1];
    const float* emb    = (const float*)d_in[2];
    const float* We     = (const float*)d_in[3];
    const float* Wh     = (const float*)d_in[4];
    const float* Wo     = (const float*)d_in[5];
    float* out = (float*)d_out;

    prep_kernel<<<VOCAB, H>>>(emb, We);
    rnn_kernel<<<BATCH / NROW, NTHR>>>(x, hidden, Wh, Wo, out, out_size);
}